// round 16
// baseline (speedup 1.0000x reference)
#include <cuda_runtime.h>
#include <cstdint>

// out[i,m,l] = w1[i,0]*t4[i,(m-1)%56,l] + w1[i,1]*t4[i,(m-2)%56,l]
// t4 as GEMM over input channels j (K=64 per conv tap; tap = A row shift):
//   D[r, i'] += Xsel[p = r + tap][j] * w2[ibase+i'][3j+tap]
// D rows 0..55 -> t4[na] (l=r), 64..119 -> t4[nb] (l=r-64).
// TF32 mma.sync m16n8k8, single pass. Grid (iq=4, m=56) = 224 blocks,
// 512 threads, TWO blocks/SM. Each thread's 24 B scalars (one w2 row) are
// loaded into REGISTERS during the prologue, overlapped with the A fill:
// the post-barrier mainloop is pure LDS+MMA.

static constexpr int A_W     = 68;     // words/row; frag bank = (4g+q)%32 -> conflict-free
static constexpr int A_ROWS  = 132;
static constexpr int OFF_R_W = A_ROWS * A_W;              // 8976
static constexpr int RBUF_W  = 8 * 32 * 9;                // 2304 (stride 9: conflict-free)
static constexpr int SMEM_TOTAL = (OFF_R_W + RBUF_W) * 4; // 45120 B (x2/SM = 90 KB)

__device__ __forceinline__ uint32_t f2tf32(float v) {
    uint32_t r; asm("cvt.rna.tf32.f32 %0, %1;" : "=r"(r) : "f"(v)); return r;
}
__device__ __forceinline__ void mma_tf32(float* d, const uint32_t* a, const uint32_t* b) {
    asm("mma.sync.aligned.m16n8k8.row.col.f32.tf32.tf32.f32 "
        "{%0,%1,%2,%3}, {%4,%5,%6,%7}, {%8,%9}, {%0,%1,%2,%3};"
        : "+f"(d[0]), "+f"(d[1]), "+f"(d[2]), "+f"(d[3])
        : "r"(a[0]), "r"(a[1]), "r"(a[2]), "r"(a[3]), "r"(b[0]), "r"(b[1]));
}

__global__ __launch_bounds__(512, 2) void tf32_kernel(
    const float* __restrict__ x,
    const float* __restrict__ w1,
    const float* __restrict__ w2,
    float* __restrict__ out) {

    extern __shared__ uint32_t smem[];
    uint32_t* A = smem;                                    // [132][68]
    float*    R = reinterpret_cast<float*>(smem + OFF_R_W);

    const int tid  = threadIdx.x;
    const int wid  = tid >> 5;
    const int lane = tid & 31;

    const int m     = blockIdx.y;
    const int iq    = blockIdx.x;          // channel quarter
    const int ibase = iq * 16;
    const int na    = (m + 55) % 56;
    const int nb    = (m + 54) % 56;

    const int g    = lane >> 2;            // 0..7
    const int q    = lane & 3;             // 0..3
    const int mt0  = wid & 3;              // m-tiles (mt0, mt0+4)
    const int nt   = (wid >> 2) & 1;       // n-tile: cols nt*8 .. nt*8+7
    const int kh   = wid >> 3;             // k-half 0/1
    const int kbase = kh * 12;

    // ---- Prologue gmem reads, all independent (batch early, high MLP) ----
    float w1r[2][2];
#pragma unroll
    for (int e = 0; e < 2; ++e) {
        int c = ibase + nt * 8 + 2 * q + e;
        w1r[e][0] = __ldg(&w1[2 * c]);
        w1r[e][1] = __ldg(&w1[2 * c + 1]);
    }
    // B operands into registers: bfr[s] = {w2row[3*(kc)+tap], w2row[3*(kc+4)+tap]}
    const float* brow = &w2[(ibase + nt * 8 + g) * 192 + 3 * q];
    uint32_t breg[12][2];
#pragma unroll
    for (int s = 0; s < 12; ++s) {
        const int kidx = kbase + s;
        const int tap  = kidx >> 3;
        const int ks   = kidx & 7;
        breg[s][0] = f2tf32(__ldg(brow + 24 * ks + tap));
        breg[s][1] = f2tf32(__ldg(brow + 24 * ks + 12 + tap));
    }

    // Zero halo rows {0, 57, 64, 121} (272 words).
    if (tid < 272) {
        int r = tid / 68, w = tid - r * 68;
        int row = (r == 0) ? 0 : (r == 1) ? 57 : (r == 2) ? 64 : 121;
        A[row * A_W + w] = 0u;
    }

    // Fill A: item = (sel, jg, l); 4 j-consecutive channels -> one STS.128.
#pragma unroll
    for (int it = 0; it < 4; ++it) {
        int idx = it * 512 + tid;              // valid < 1792
        if (idx < 1792) {
            int sel = idx >= 896;
            int rem = idx - sel * 896;
            int jg  = rem / 56;
            int l   = rem - jg * 56;
            int n   = sel ? nb : na;
            int p   = sel * 64 + 1 + l;
            const float* xp = &x[(jg * 4) * 3136 + n * 56 + l];
            uint4 v;
            v.x = f2tf32(xp[0]);
            v.y = f2tf32(xp[3136]);
            v.z = f2tf32(xp[2 * 3136]);
            v.w = f2tf32(xp[3 * 3136]);
            *reinterpret_cast<uint4*>(&A[p * A_W + jg * 4]) = v;
        }
    }

    __syncthreads();   // waits only on the A fill

    // ---- Mainloop: 12 k-steps, pure LDS + MMA ----
    float d[2][4];
#pragma unroll
    for (int h = 0; h < 2; ++h)
#pragma unroll
        for (int c = 0; c < 4; ++c) d[h][c] = 0.0f;

#pragma unroll
    for (int s = 0; s < 12; ++s) {
        const int kidx = kbase + s;
        const int tap  = kidx >> 3;
        const int kc   = ((kidx & 7) << 3) + q;
        uint32_t afr[2][4];
#pragma unroll
        for (int h = 0; h < 2; ++h) {
            const int r0 = (mt0 + 4 * h) * 16 + g + tap;
            const uint32_t* p = &A[r0 * A_W + kc];
            afr[h][0] = p[0];
            afr[h][1] = p[8 * A_W];
            afr[h][2] = p[4];
            afr[h][3] = p[8 * A_W + 4];
        }
#pragma unroll
        for (int h = 0; h < 2; ++h)
            mma_tf32(d[h], afr[h], breg[s]);
    }

    // ---- Pair reduction: kh=1 dumps partials, kh=0 adds ----
    if (kh == 1) {
        float* dst = &R[((wid - 8) * 32 + lane) * 9];
#pragma unroll
        for (int h = 0; h < 2; ++h)
#pragma unroll
            for (int c = 0; c < 4; ++c) dst[h * 4 + c] = d[h][c];
    }
    __syncthreads();

    if (kh == 0) {
        const float* src = &R[(wid * 32 + lane) * 9];
#pragma unroll
        for (int h = 0; h < 2; ++h)
#pragma unroll
            for (int c = 0; c < 4; ++c) d[h][c] += src[h * 4 + c];

        // ---- Register epilogue ----
        const int l1 = mt0 * 16 + g;       // < 56 always
        const int l2 = l1 + 8;             // invalid when mt0 == 3
#pragma unroll
        for (int e = 0; e < 2; ++e) {
            const int c = ibase + nt * 8 + 2 * q + e;
            float* orow = &out[(c * 56 + m) * 56];
            orow[l1] = fmaf(w1r[e][0], d[0][e], w1r[e][1] * d[1][e]);
            if (l2 < 56)
                orow[l2] = fmaf(w1r[e][0], d[0][2 + e], w1r[e][1] * d[1][2 + e]);
        }
    }
}

extern "C" void kernel_launch(void* const* d_in, const int* in_sizes, int n_in,
                              void* d_out, int out_size) {
    const float* x  = (const float*)d_in[0];   // (1,64,56,56)
    const float* w1 = (const float*)d_in[1];   // (64,2)
    const float* w2 = (const float*)d_in[2];   // (64,64,3)
    float* out = (float*)d_out;                // (1,64,56,56)

    cudaFuncSetAttribute(tf32_kernel,
                         cudaFuncAttributeMaxDynamicSharedMemorySize, SMEM_TOTAL);

    dim3 grid(4, 56);
    tf32_kernel<<<grid, 512, SMEM_TOTAL>>>(x, w1, w2, out);
}

// round 17
// speedup vs baseline: 1.4723x; 1.4723x over previous
#include <cuda_runtime.h>
#include <cstdint>

// out[i,m,l] = w1[i,0]*t4[i,(m-1)%56,l] + w1[i,1]*t4[i,(m-2)%56,l]
// t4 as GEMM over input channels j (K=64 per conv tap; tap = A row shift):
//   D[r, i'] += Xsel[p = r + tap][j] * w2[ibase+i'][3j+tap]
// D rows 0..55 -> t4[na] (l=r), 64..119 -> t4[nb] (l=r-64).
// TF32 mma.sync m16n8k8, single pass. Grid (iq=8, m=56) = 448 blocks,
// 256 threads, FOUR blocks/SM (__launch_bounds__(256,4)): co-resident block
// chains cover each other's prologue/barrier stalls. Warp pair (w, w+4)
// splits the 24 k-steps 12/12; register w1-mix epilogue.

static constexpr int A_W     = 68;     // words/row; frag bank = (4g+q)%32 -> conflict-free
static constexpr int A_ROWS  = 132;
static constexpr int OFF_B_W = A_ROWS * A_W;              // 8976
static constexpr int B_ROWS  = 24;                        // 3 taps x 8 channels
static constexpr int OFF_R_W = OFF_B_W + B_ROWS * A_W;    // 10608
static constexpr int RBUF_W  = 4 * 32 * 9;                // 1152 (stride 9: conflict-free)
static constexpr int SMEM_TOTAL = (OFF_R_W + RBUF_W) * 4; // 47040 B (x4/SM = 188 KB)

__device__ __forceinline__ uint32_t f2tf32(float v) {
    uint32_t r; asm("cvt.rna.tf32.f32 %0, %1;" : "=r"(r) : "f"(v)); return r;
}
__device__ __forceinline__ void mma_tf32(float* d, const uint32_t* a, const uint32_t* b) {
    asm("mma.sync.aligned.m16n8k8.row.col.f32.tf32.tf32.f32 "
        "{%0,%1,%2,%3}, {%4,%5,%6,%7}, {%8,%9}, {%0,%1,%2,%3};"
        : "+f"(d[0]), "+f"(d[1]), "+f"(d[2]), "+f"(d[3])
        : "r"(a[0]), "r"(a[1]), "r"(a[2]), "r"(a[3]), "r"(b[0]), "r"(b[1]));
}

__global__ __launch_bounds__(256, 4) void tf32_kernel(
    const float* __restrict__ x,
    const float* __restrict__ w1,
    const float* __restrict__ w2,
    float* __restrict__ out) {

    extern __shared__ uint32_t smem[];
    uint32_t* A = smem;                  // [132][68]: A[p][j]  (tf32 bits)
    uint32_t* B = smem + OFF_B_W;        // [24][68]:  B[tap*8+i'][j]
    float*    R = reinterpret_cast<float*>(smem + OFF_R_W);

    const int tid  = threadIdx.x;
    const int wid  = tid >> 5;
    const int lane = tid & 31;

    const int m     = blockIdx.y;
    const int iq    = blockIdx.x;          // channel eighth
    const int ibase = iq * 8;
    const int na    = (m + 55) % 56;
    const int nb    = (m + 54) % 56;

    // Warp tile coords + w1 preload first (independent LDGs batch early).
    const int g    = lane >> 2;            // 0..7
    const int q    = lane & 3;             // 0..3
    const int mt0  = wid & 3;              // m-tiles (mt0, mt0+4)
    const int kh   = wid >> 2;             // k-half 0/1
    float w1r[2][2];
#pragma unroll
    for (int e = 0; e < 2; ++e) {
        int c = ibase + 2 * q + e;
        w1r[e][0] = __ldg(&w1[2 * c]);
        w1r[e][1] = __ldg(&w1[2 * c + 1]);
    }

    // Zero halo rows {0, 57, 64, 121} (272 words).
    if (tid < 256) {
        int r = tid / 68, w = tid - r * 68;
        int row = (r == 0) ? 0 : (r == 1) ? 57 : (r == 2) ? 64 : 121;
        A[row * A_W + w] = 0u;
    }
    if (tid < 16) {   // remaining 16 words of the 272
        int idx = 256 + tid;
        int r = idx / 68, w = idx - r * 68;   // r == 3
        A[121 * A_W + w] = 0u;
        (void)r;
    }

    // Fill A: item = (sel, jg, l); 4 j-consecutive channels -> one STS.128.
#pragma unroll
    for (int it = 0; it < 7; ++it) {
        int idx = it * 256 + tid;              // 0..1791
        int sel = idx >= 896;
        int rem = idx - sel * 896;
        int jg  = rem / 56;
        int l   = rem - jg * 56;
        int n   = sel ? nb : na;
        int p   = sel * 64 + 1 + l;
        const float* xp = &x[(jg * 4) * 3136 + n * 56 + l];
        uint4 v;
        v.x = f2tf32(xp[0]);
        v.y = f2tf32(xp[3136]);
        v.z = f2tf32(xp[2 * 3136]);
        v.w = f2tf32(xp[3 * 3136]);
        *reinterpret_cast<uint4*>(&A[p * A_W + jg * 4]) = v;
    }

    // Fill B (this eighth's 8 channels) from float4 loads of w2.
#pragma unroll
    for (int it = 0; it < 2; ++it) {
        int idx = it * 256 + tid;              // valid < 384 (8 ch * 48 float4)
        if (idx < 384) {
            int i  = idx / 48;
            int f4 = idx - i * 48;
            float4 v = *reinterpret_cast<const float4*>(&w2[(ibase + i) * 192 + f4 * 4]);
            float vv[4] = {v.x, v.y, v.z, v.w};
#pragma unroll
            for (int e = 0; e < 4; ++e) {
                int jk  = f4 * 4 + e;
                int j   = jk / 3;
                int tap = jk - 3 * j;
                B[(tap * 8 + i) * A_W + j] = f2tf32(vv[e]);
            }
        }
    }

    __syncthreads();

    // ---- Mainloop: 12 k-steps (kidx = kh*12 + s) ----
    float d[2][4];
#pragma unroll
    for (int h = 0; h < 2; ++h)
#pragma unroll
        for (int c = 0; c < 4; ++c) d[h][c] = 0.0f;

    const int kbase = kh * 12;
#pragma unroll
    for (int s = 0; s < 12; ++s) {
        const int kidx = kbase + s;
        const int tap  = kidx >> 3;
        const int kc   = ((kidx & 7) << 3) + q;
        uint32_t afr[2][4], bfr[2];
#pragma unroll
        for (int h = 0; h < 2; ++h) {
            const int r0 = (mt0 + 4 * h) * 16 + g + tap;
            const uint32_t* p = &A[r0 * A_W + kc];
            afr[h][0] = p[0];
            afr[h][1] = p[8 * A_W];
            afr[h][2] = p[4];
            afr[h][3] = p[8 * A_W + 4];
        }
        {
            const uint32_t* p = &B[(tap * 8 + g) * A_W + kc];
            bfr[0] = p[0];
            bfr[1] = p[4];
        }
#pragma unroll
        for (int h = 0; h < 2; ++h)
            mma_tf32(d[h], afr[h], bfr);
    }

    // ---- Pair reduction: kh=1 dumps partials, kh=0 adds ----
    if (kh == 1) {
        float* dst = &R[((wid - 4) * 32 + lane) * 9];
#pragma unroll
        for (int h = 0; h < 2; ++h)
#pragma unroll
            for (int c = 0; c < 4; ++c) dst[h * 4 + c] = d[h][c];
    }
    __syncthreads();

    if (kh == 0) {
        const float* src = &R[(wid * 32 + lane) * 9];
#pragma unroll
        for (int h = 0; h < 2; ++h)
#pragma unroll
            for (int c = 0; c < 4; ++c) d[h][c] += src[h * 4 + c];

        // ---- Register epilogue ----
        const int l1 = mt0 * 16 + g;       // < 56 always
        const int l2 = l1 + 8;             // invalid when mt0 == 3
#pragma unroll
        for (int e = 0; e < 2; ++e) {
            const int c = ibase + 2 * q + e;
            float* orow = &out[(c * 56 + m) * 56];
            orow[l1] = fmaf(w1r[e][0], d[0][e], w1r[e][1] * d[1][e]);
            if (l2 < 56)
                orow[l2] = fmaf(w1r[e][0], d[0][2 + e], w1r[e][1] * d[1][2 + e]);
        }
    }
}

extern "C" void kernel_launch(void* const* d_in, const int* in_sizes, int n_in,
                              void* d_out, int out_size) {
    const float* x  = (const float*)d_in[0];   // (1,64,56,56)
    const float* w1 = (const float*)d_in[1];   // (64,2)
    const float* w2 = (const float*)d_in[2];   // (64,64,3)
    float* out = (float*)d_out;                // (1,64,56,56)

    cudaFuncSetAttribute(tf32_kernel,
                         cudaFuncAttributeMaxDynamicSharedMemorySize, SMEM_TOTAL);

    dim3 grid(8, 56);
    tf32_kernel<<<grid, 256, SMEM_TOTAL>>>(x, w1, w2, out);
}